// round 17
// baseline (speedup 1.0000x reference)
#include <cuda_runtime.h>
#include <cstdint>
#include <cstddef>

// Problem constants
#define Bv   128
#define Tv   512
#define Vv   32000
#define Ev   256
#define Hv   128
#define G4H  512      // 4*H (gate columns per direction)
#define NW   1024     // 4H * 2 directions (concat fw|bw)

// Scratch: embW = emb @ [W_fw | W_bw] + [b_fw | b_bw]   (131 MB, device global)
__device__ float g_embW[(size_t)Vv * NW];

// ---------------------------------------------------------------------------
// f32x2 packed-math helpers (sm_103a; ptxas never emits FFMA2 from C++)
// ---------------------------------------------------------------------------
__device__ __forceinline__ unsigned long long fma2(unsigned long long a,
                                                   unsigned long long b,
                                                   unsigned long long c) {
    unsigned long long d;
    asm("fma.rn.f32x2 %0, %1, %2, %3;" : "=l"(d) : "l"(a), "l"(b), "l"(c));
    return d;
}
__device__ __forceinline__ unsigned long long dup2(float x) {
    unsigned long long d;
    asm("mov.b64 %0, {%1, %1};" : "=l"(d) : "f"(x));
    return d;
}
__device__ __forceinline__ unsigned long long pack2(float lo, float hi) {
    unsigned long long d;
    asm("mov.b64 %0, {%1, %2};" : "=l"(d) : "f"(lo), "f"(hi));
    return d;
}
__device__ __forceinline__ void unpack2(unsigned long long v, float& lo, float& hi) {
    asm("mov.b64 {%0, %1}, %2;" : "=f"(lo), "=f"(hi) : "l"(v));
}

// MUFU-direct activations (no divides, ~2-ulp accurate)
__device__ __forceinline__ float ex2f(float x) {
    float y; asm("ex2.approx.f32 %0, %1;" : "=f"(y) : "f"(x)); return y;
}
__device__ __forceinline__ float rcpf(float x) {
    float y; asm("rcp.approx.f32 %0, %1;" : "=f"(y) : "f"(x)); return y;
}
#define LOG2E 1.4426950408889634f
__device__ __forceinline__ float sigmoid_f(float x) {
    return rcpf(1.0f + ex2f(-LOG2E * x));          // 1/(1+e^-x)
}
__device__ __forceinline__ float tanh_f(float x) {
    return fmaf(-2.0f, rcpf(1.0f + ex2f(2.0f * LOG2E * x)), 1.0f); // 1-2/(1+e^2x)
}

// ---------------------------------------------------------------------------
// Kernel 1: embW[v][n] = sum_k emb[v][k] * W[k][n] + bias[n]
// M=32000, K=256, N=1024. 128x128 tile, BK=8, 256 threads, 8x8 per thread.
// ---------------------------------------------------------------------------
__global__ __launch_bounds__(256) void embw_gemm_kernel(
    const float* __restrict__ emb,
    const float* __restrict__ Wfw, const float* __restrict__ Wbw,
    const float* __restrict__ bfw, const float* __restrict__ bbw)
{
    __shared__ float As[8][128];
    __shared__ float Bs[8][128];

    const int tid = threadIdx.x;
    const int m0 = blockIdx.x * 128;
    const int n0 = blockIdx.y * 128;

    const float* Wp;
    const float* bp;
    int nb;
    if (n0 < G4H) { Wp = Wfw; bp = bfw; nb = n0; }
    else          { Wp = Wbw; bp = bbw; nb = n0 - G4H; }

    const int ar = tid >> 1;
    const int ac = (tid & 1) * 4;
    const int br = tid >> 5;
    const int bc = (tid & 31) * 4;
    const int tx = tid & 15;
    const int ty = tid >> 4;

    unsigned long long acc[8][4];
#pragma unroll
    for (int i = 0; i < 8; i++)
#pragma unroll
        for (int j2 = 0; j2 < 4; j2++) acc[i][j2] = 0ull;

    float4 av = *(const float4*)&emb[(size_t)(m0 + ar) * Ev + ac];
    float4 bv = *(const float4*)&Wp[(size_t)br * G4H + nb + bc];

    for (int kt = 0; kt < Ev / 8; ++kt) {
        As[ac + 0][ar] = av.x; As[ac + 1][ar] = av.y;
        As[ac + 2][ar] = av.z; As[ac + 3][ar] = av.w;
        *(float4*)&Bs[br][bc] = bv;
        __syncthreads();
        if (kt + 1 < Ev / 8) {
            int k0 = (kt + 1) * 8;
            av = *(const float4*)&emb[(size_t)(m0 + ar) * Ev + k0 + ac];
            bv = *(const float4*)&Wp[(size_t)(k0 + br) * G4H + nb + bc];
        }
#pragma unroll
        for (int kk = 0; kk < 8; ++kk) {
            float a[8];
            *(float4*)&a[0] = *(const float4*)&As[kk][ty * 8];
            *(float4*)&a[4] = *(const float4*)&As[kk][ty * 8 + 4];
            ulonglong2 b0 = *(const ulonglong2*)&Bs[kk][tx * 8];
            ulonglong2 b1 = *(const ulonglong2*)&Bs[kk][tx * 8 + 4];
#pragma unroll
            for (int i = 0; i < 8; i++) {
                unsigned long long ad = dup2(a[i]);
                acc[i][0] = fma2(ad, b0.x, acc[i][0]);
                acc[i][1] = fma2(ad, b0.y, acc[i][1]);
                acc[i][2] = fma2(ad, b1.x, acc[i][2]);
                acc[i][3] = fma2(ad, b1.y, acc[i][3]);
            }
        }
        __syncthreads();
    }

    float bias[8];
    *(float4*)&bias[0] = *(const float4*)&bp[nb + tx * 8];
    *(float4*)&bias[4] = *(const float4*)&bp[nb + tx * 8 + 4];
#pragma unroll
    for (int i = 0; i < 8; i++) {
        int row = m0 + ty * 8 + i;
        float c[8];
#pragma unroll
        for (int j2 = 0; j2 < 4; j2++)
            unpack2(acc[i][j2], c[2 * j2], c[2 * j2 + 1]);
        float4 v0, v1;
        v0.x = c[0] + bias[0]; v0.y = c[1] + bias[1];
        v0.z = c[2] + bias[2]; v0.w = c[3] + bias[3];
        v1.x = c[4] + bias[4]; v1.y = c[5] + bias[5];
        v1.z = c[6] + bias[6]; v1.w = c[7] + bias[7];
        *(float4*)&g_embW[(size_t)row * NW + n0 + tx * 8]     = v0;
        *(float4*)&g_embW[(size_t)row * NW + n0 + tx * 8 + 4] = v1;
    }
}

// ---------------------------------------------------------------------------
// Kernel 2: persistent LSTM recurrence. 256 threads, 1 block/SM.
// grid = 128: blockIdx.x&1 = direction, >>1 = batch pair.
// Intra-warp gate pairing: thread 2m   = (i,g) of cell m  (cols m, m+256)
//                          thread 2m+1 = (f,o) of cell m  (cols m+128, m+384)
// (i,g) lane computes p = i*g, hands to neighbor via SHFL.BFLY; (f,o) lane
// carries c and runs the epilogue. h is PING-PONG double-buffered so the
// write of h(t) can never race the FMA-loop reads of h(t-1): one
// __syncthreads per step (which also drains the h STS) is then sufficient.
// f32x2 lanes = (even-k, odd-k) partials; U packed once: 44 k-pairs/col in
// u64 regs + 10 smem quads/col. MUFU activations, branch-free.
// ---------------------------------------------------------------------------
#define NPR   44
#define NQS   10
// smem: Uq[10][512] float4 + hbuf[2][2][128] f32 + tokb[2][512] int
#define LSTM_SMEM_BYTES (NQS * G4H * 16 + 512 * 4 + 1024 * 4)

__global__ __launch_bounds__(256, 1) void lstm_kernel(
    const void*  __restrict__ tokens,
    const float* __restrict__ Ufw,
    const float* __restrict__ Ubw,
    float* __restrict__ out)
{
    extern __shared__ float smemf[];
    float4* Uq    = (float4*)smemf;                     // [NQS][512]
    float*  hbufA = (float*)(Uq + NQS * G4H);           // [2][128] buffer 0
    float*  hbufB = hbufA + 256;                        // [2][128] buffer 1
    int*    tokb  = (int*)(hbufB + 256);                // [2][512]
    __shared__ int s_cnt;

    const int t    = threadIdx.x;
    const int m    = t >> 1;                 // cell index 0..127
    const int role = t & 1;                  // 0 = (i,g), 1 = (f,o)
    const int j0   = m + (role << 7);        // i or f column
    const int j1   = j0 + 256;               // g or o column
    const int dir  = blockIdx.x & 1;
    const int b0   = (blockIdx.x >> 1) * 2;
    const float* U = dir ? Ubw : Ufw;

    // per-thread activation constants for the j1 gate (g->tanh, o->sigmoid)
    const float a2 = role ? -LOG2E : 2.0f * LOG2E;
    const float b2 = role ? 1.0f   : -2.0f;
    const float c2 = role ? 0.0f   : 1.0f;

    // ---- inline tokens-dtype detection (first 8 KB, in-bounds either way) ----
    if (t == 0) s_cnt = 0;
    __syncthreads();
    {
        const unsigned int* w = (const unsigned int*)tokens;
        int local = 0;
        for (int i = t; i < 1024; i += 256)
            if (w[2 * i + 1] == 0u) local++;
        atomicAdd(&s_cnt, local);
    }
    __syncthreads();
    const int is64 = (s_cnt > 512);

    // ---- pack U k-pairs into registers (k rows 0..2*NPR-1) ----
    unsigned long long Ur0[NPR], Ur1[NPR];
#pragma unroll
    for (int p = 0; p < NPR; p++) {
        Ur0[p] = pack2(U[(2 * p) * G4H + j0], U[(2 * p + 1) * G4H + j0]);
        Ur1[p] = pack2(U[(2 * p) * G4H + j1], U[(2 * p + 1) * G4H + j1]);
    }

    // ---- U rows 88..127 into smem quads: Uq[q][col] = U[88+4q..+3][col] ----
    for (int idx = t; idx < NQS * G4H; idx += 256) {
        int q = idx >> 9;
        int col = idx & 511;
        int k = 2 * NPR + 4 * q;
        float4 v;
        v.x = U[(k + 0) * G4H + col];
        v.y = U[(k + 1) * G4H + col];
        v.z = U[(k + 2) * G4H + col];
        v.w = U[(k + 3) * G4H + col];
        Uq[q * G4H + col] = v;
    }

    // ---- tokens for rows b0, b0+1 ----
    for (int idx = t; idx < 2 * Tv; idx += 256) {
        int r  = idx >> 9;
        int tt = idx & (Tv - 1);
        int tok;
        if (is64) tok = (int)((const long long*)tokens)[(size_t)(b0 + r) * Tv + tt];
        else      tok =       ((const int*)tokens)      [(size_t)(b0 + r) * Tv + tt];
        tokb[idx] = tok;
    }
    if (t < 128) { hbufA[t] = 0.0f; hbufA[128 + t] = 0.0f; }  // h(-1) = 0
    __syncthreads();

    const int cbase = dir * G4H;
    const float* eb = g_embW;
    float c0 = 0.0f, c1 = 0.0f, hl0 = 0.0f, hl1 = 0.0f;

    // initial xw prefetch: [col][row]
    int t0 = dir ? (Tv - 1) : 0;
    int tk0 = tokb[t0], tk1 = tokb[Tv + t0];
    float xw00 = eb[(size_t)tk0 * NW + cbase + j0];
    float xw01 = eb[(size_t)tk1 * NW + cbase + j0];
    float xw10 = eb[(size_t)tk0 * NW + cbase + j1];
    float xw11 = eb[(size_t)tk1 * NW + cbase + j1];

    float* hcur = hbufA;    // read h(t-1) from here
    float* hnxt = hbufB;    // write h(t) here

    for (int s = 0; s < Tv; ++s) {
        const int tc = dir ? (Tv - 1 - s) : s;

        // prefetch next step's xw (hidden behind FMA loop)
        float nx00 = 0.0f, nx01 = 0.0f, nx10 = 0.0f, nx11 = 0.0f;
        if (s + 1 < Tv) {
            int tn = dir ? (tc - 1) : (tc + 1);
            int a = tokb[tn], b = tokb[Tv + tn];
            nx00 = eb[(size_t)a * NW + cbase + j0];
            nx01 = eb[(size_t)b * NW + cbase + j0];
            nx10 = eb[(size_t)a * NW + cbase + j1];
            nx11 = eb[(size_t)b * NW + cbase + j1];
        }

        const ulonglong2* h0q = (const ulonglong2*)hcur;
        const ulonglong2* h1q = (const ulonglong2*)(hcur + 128);

        // acc[col][row], lanes = (even-k partial, odd-k partial)
        unsigned long long a00 = pack2(xw00, 0.0f);
        unsigned long long a01 = pack2(xw01, 0.0f);
        unsigned long long a10 = pack2(xw10, 0.0f);
        unsigned long long a11 = pack2(xw11, 0.0f);

#pragma unroll
        for (int q = 0; q < NPR / 2; q++) {
            ulonglong2 h0 = h0q[q];
            ulonglong2 h1 = h1q[q];
            a00 = fma2(h0.x, Ur0[2 * q],     a00);
            a00 = fma2(h0.y, Ur0[2 * q + 1], a00);
            a01 = fma2(h1.x, Ur0[2 * q],     a01);
            a01 = fma2(h1.y, Ur0[2 * q + 1], a01);
            a10 = fma2(h0.x, Ur1[2 * q],     a10);
            a10 = fma2(h0.y, Ur1[2 * q + 1], a10);
            a11 = fma2(h1.x, Ur1[2 * q],     a11);
            a11 = fma2(h1.y, Ur1[2 * q + 1], a11);
        }
        const ulonglong2* Uqv = (const ulonglong2*)Uq;
#pragma unroll
        for (int q = NPR / 2; q < 32; q++) {
            ulonglong2 h0 = h0q[q];
            ulonglong2 h1 = h1q[q];
            ulonglong2 ua = Uqv[(q - NPR / 2) * G4H + j0];
            ulonglong2 ub = Uqv[(q - NPR / 2) * G4H + j1];
            a00 = fma2(h0.x, ua.x, a00);
            a00 = fma2(h0.y, ua.y, a00);
            a01 = fma2(h1.x, ua.x, a01);
            a01 = fma2(h1.y, ua.y, a01);
            a10 = fma2(h0.x, ub.x, a10);
            a10 = fma2(h0.y, ub.y, a10);
            a11 = fma2(h1.x, ub.x, a11);
            a11 = fma2(h1.y, ub.y, a11);
        }

        float lo, hi;
        float z00, z01, z10, z11;
        unpack2(a00, lo, hi); z00 = lo + hi;
        unpack2(a01, lo, hi); z01 = lo + hi;
        unpack2(a10, lo, hi); z10 = lo + hi;
        unpack2(a11, lo, hi); z11 = lo + hi;

        // u = sigmoid(z00/z01): i (role0) or f (role1)
        float u0 = sigmoid_f(z00), u1 = sigmoid_f(z01);
        // v = act2(z10/z11): g=tanh (role0) or o=sigmoid (role1), branch-free
        float v0 = fmaf(b2, rcpf(1.0f + ex2f(a2 * z10)), c2);
        float v1 = fmaf(b2, rcpf(1.0f + ex2f(a2 * z11)), c2);

        // role0 produces p = i*g; neighbor exchange via SHFL.BFLY (xor 1)
        float p0 = u0 * v0;
        float p1 = u1 * v1;
        float q0 = __shfl_xor_sync(0xffffffffu, p0, 1);
        float q1 = __shfl_xor_sync(0xffffffffu, p1, 1);

        if (role) {
            // this lane holds f (u) and o (v); q = i*g from neighbor
            c0 = fmaf(u0, c0, q0);
            c1 = fmaf(u1, c1, q1);
            hl0 = v0 * tanh_f(c0);
            hl1 = v1 * tanh_f(c1);
            hnxt[m]       = hl0;        // write h(t) to the OTHER buffer
            hnxt[128 + m] = hl1;
            out[((size_t)b0 * Tv + tc) * 256 + dir * 128 + m]       = hl0;
            out[((size_t)(b0 + 1) * Tv + tc) * 256 + dir * 128 + m] = hl1;
        }
        __syncthreads();      // h(t) visible; all reads of hcur complete
        { float* tmp = hcur; hcur = hnxt; hnxt = tmp; }
        xw00 = nx00; xw01 = nx01; xw10 = nx10; xw11 = nx11;
    }

    // final states: after out[B,T,2H]: h_fw, c_fw, h_bw, c_bw (each [B,H])
    if (role) {
        size_t fin  = (size_t)Bv * Tv * 256;
        size_t hoff = fin + (size_t)(dir * 2) * (Bv * Hv);
        out[hoff + (size_t)b0 * Hv + m]                 = hl0;
        out[hoff + (size_t)(b0 + 1) * Hv + m]           = hl1;
        out[hoff + Bv * Hv + (size_t)b0 * Hv + m]       = c0;
        out[hoff + Bv * Hv + (size_t)(b0 + 1) * Hv + m] = c1;
    }
}

// ---------------------------------------------------------------------------
// Inputs (metadata order): tokens, emb, W_fw, U_fw, b_fw, W_bw, U_bw, b_bw
// Output: out[B,T,2H] fp32, then h_fw, c_fw, h_bw, c_bw (each [B,H])
// ---------------------------------------------------------------------------
extern "C" void kernel_launch(void* const* d_in, const int* in_sizes, int n_in,
                              void* d_out, int out_size)
{
    const void*  tokens = d_in[0];
    const float* emb = (const float*)d_in[1];
    const float* Wfw = (const float*)d_in[2];
    const float* Ufw = (const float*)d_in[3];
    const float* bfw = (const float*)d_in[4];
    const float* Wbw = (const float*)d_in[5];
    const float* Ubw = (const float*)d_in[6];
    const float* bbw = (const float*)d_in[7];
    float* out = (float*)d_out;

    (void)in_sizes; (void)n_in; (void)out_size;

    dim3 ggrid(Vv / 128, NW / 128);
    embw_gemm_kernel<<<ggrid, 256>>>(emb, Wfw, Wbw, bfw, bbw);

    cudaFuncSetAttribute(lstm_kernel,
                         cudaFuncAttributeMaxDynamicSharedMemorySize,
                         LSTM_SMEM_BYTES);
    lstm_kernel<<<128, 256, LSTM_SMEM_BYTES>>>(tokens, Ufw, Ubw, out);
}